// round 15
// baseline (speedup 1.0000x reference)
#include <cuda_runtime.h>
#include <cuda_fp16.h>
#include <cuda_bf16.h>
#include <math.h>

#define DS   128
#define DSM  127
#define D3   (DS * DS * DS)

typedef unsigned long long u64;

// Tile: 32 x 8 x 8 real cells = 2048; 384 threads, 3 blocks/SM.
#define TXD   32
#define TYD   8
#define TZD   8
#define CELLS (TXD * TYD * TZD)  // 2048
#define NTHR  384

// Halo padded in x to 40 so interior quads are 16B-aligned for STS.128.
#define SHX  40
#define SHY  12
#define SHZ  12
#define HXY  (SHX * SHY)         // 480
#define HTOT (HXY * SHZ)         // 5760

// Stencil rows (oz,oy) with s2_yz <= 5 (s2_total <= 6 reachable): 21 rows.
// Pattern = allowed ox bits (bit p => ox = p-2) for s2_total <= 6.
#define NROW 21
__device__ __constant__ int  cROZ[NROW]  = {-2,-2,-2,-1,-1,-1,-1,-1, 0,0,0,0,0, 1,1,1,1,1, 2,2,2};
__device__ __constant__ int  cROY[NROW]  = {-1, 0, 1,-2,-1, 0, 1, 2,-2,-1,0,1,2,-2,-1,0,1,2,-1,0,1};
__device__ __constant__ int  cPAT[NROW]  = {0x0E,0x0E,0x0E,0x0E,0x1F,0x1F,0x1F,0x0E,
                                            0x0E,0x1F,0x1B,0x1F,0x0E,
                                            0x0E,0x1F,0x1F,0x1F,0x0E,0x0E,0x0E,0x0E};

struct SM {
    uint2          W01[HTOT];    // .x = f16(jx)|f16(jy)<<16, .y = f16(jz)|bf16(vz)<<16
    unsigned int   W2[HTOT];     // bf16(vx)|bf16(vy)<<16
    u64            OCC[SHY * SHZ];   // per-(y,z)-row occupancy bits by slot
    float4         ROWT[NROW];   // {int_as_float(oz*HXY+oy*SHX), oyf, ozf, 0}
    unsigned short list[CELLS];
    int            cnt;
};

__device__ __forceinline__ float fast_rsqrt(float x) {
    float r; asm("rsqrt.approx.f32 %0, %1;" : "=f"(r) : "f"(x)); return r;
}
__device__ __forceinline__ float f16lo(unsigned int w) {
    return __half2float(__ushort_as_half((unsigned short)(w & 0xFFFFu)));
}
__device__ __forceinline__ float f16hi(unsigned int w) {
    return __half2float(__ushort_as_half((unsigned short)(w >> 16)));
}
__device__ __forceinline__ float bflo(unsigned int w) {
    return __uint_as_float(w << 16);
}
__device__ __forceinline__ float bfhi(unsigned int w) {
    return __uint_as_float(w & 0xFFFF0000u);
}
__device__ __forceinline__ unsigned int pack_w01y(float jz, float vz) {
    unsigned int h = __half_as_ushort(__float2half_rn(jz));
    unsigned int b = (unsigned int)__bfloat16_as_ushort(__float2bfloat16(vz));
    return (b << 16) | h;
}
__device__ __forceinline__ unsigned int pack_w2(float vx, float vy) {
    unsigned int a = (unsigned int)__bfloat16_as_ushort(__float2bfloat16(vx));
    unsigned int b = (unsigned int)__bfloat16_as_ushort(__float2bfloat16(vy));
    return (b << 16) | a;
}

__global__ __launch_bounds__(NTHR, 3) void dem_step(
    const float* __restrict__ xg,  const float* __restrict__ yg,
    const float* __restrict__ zg,  const float* __restrict__ vxg,
    const float* __restrict__ vyg, const float* __restrict__ vzg,
    const float* __restrict__ mg,  float* __restrict__ out, float ETA)
{
    extern __shared__ char smraw[];
    SM* S = (SM*)smraw;

    const int x0 = blockIdx.x * TXD;
    const int y0 = blockIdx.y * TYD;
    const int z0 = blockIdx.z * TZD;
    const int tid = threadIdx.x;

    // ---- Init: cnt, OCC, decode table.
    if (tid == 0) S->cnt = 0;
    if (tid < SHY * SHZ) S->OCC[tid] = 0ull;
    if (tid >= 128 && tid < 128 + NROW) {
        int r = tid - 128;
        float4 e;
        e.x = __int_as_float(cROZ[r] * HXY + cROY[r] * SHX);
        e.y = (float)cROY[r];
        e.z = (float)cROZ[r];
        e.w = 0.0f;
        S->ROWT[r] = e;
    }
    __syncthreads();

    // ---- Halo fill, phase A: interior quads, vectorized (16B-aligned).
    for (int i = tid; i < SHY * SHZ * 8; i += NTHR) {
        int q  = i & 7;
        int r  = i >> 3;
        int ly = r % SHY;
        int lz = r / SHY;
        int uy = y0 + ly - 2;
        int uz = z0 + lz - 2;
        int gx = x0 + 4 * q;                       // no x-wrap in interior
        int g  = ((uz & DSM) << 14) | ((uy & DSM) << 7) | gx;
        float4 X4  = __ldg((const float4*)(xg + g));
        float4 Y4  = __ldg((const float4*)(yg + g));
        float4 Z4  = __ldg((const float4*)(zg + g));
        float4 VX4 = __ldg((const float4*)(vxg + g));
        float4 VY4 = __ldg((const float4*)(vyg + g));
        float4 VZ4 = __ldg((const float4*)(vzg + g));
        float4 M4  = __ldg((const float4*)(mg + g));
        unsigned ob = (M4.x != 0.0f ? 1u : 0u) | (M4.y != 0.0f ? 2u : 0u) |
                      (M4.z != 0.0f ? 4u : 0u) | (M4.w != 0.0f ? 8u : 0u);
        if (ob) atomicOr(&S->OCC[r], (u64)ob << (4 * q + 4));
        float fuy = (float)uy, fuz = (float)uz;
        unsigned int x01[4];
        {
            __half2 a;
            a = __floats2half2_rn(X4.x - (float)(gx + 0), Y4.x - fuy); x01[0] = *(unsigned int*)&a;
            a = __floats2half2_rn(X4.y - (float)(gx + 1), Y4.y - fuy); x01[1] = *(unsigned int*)&a;
            a = __floats2half2_rn(X4.z - (float)(gx + 2), Y4.z - fuy); x01[2] = *(unsigned int*)&a;
            a = __floats2half2_rn(X4.w - (float)(gx + 3), Y4.w - fuy); x01[3] = *(unsigned int*)&a;
        }
        uint4 A, B, w2;
        A.x = x01[0]; A.y = pack_w01y(Z4.x - fuz, VZ4.x);
        A.z = x01[1]; A.w = pack_w01y(Z4.y - fuz, VZ4.y);
        B.x = x01[2]; B.y = pack_w01y(Z4.z - fuz, VZ4.z);
        B.z = x01[3]; B.w = pack_w01y(Z4.w - fuz, VZ4.w);
        w2.x = pack_w2(VX4.x, VY4.x);
        w2.y = pack_w2(VX4.y, VY4.y);
        w2.z = pack_w2(VX4.z, VY4.z);
        w2.w = pack_w2(VX4.w, VY4.w);
        int s = lz * HXY + ly * SHX + 4 * q + 4;   // even -> W01 16B-aligned
        *(uint4*)&S->W01[s]     = A;
        *(uint4*)&S->W01[s + 2] = B;
        *(uint4*)&S->W2[s]      = w2;
    }

    // ---- Halo fill, phase B: x-edge cells (halo lx 0,1,34,35), scalar.
    for (int i = tid; i < SHY * SHZ * 4; i += NTHR) {
        int e  = i & 3;
        int r  = i >> 2;
        int ly = r % SHY;
        int lz = r / SHY;
        int lxo = (e < 2) ? e : e + 32;            // 0,1,34,35
        int ux = x0 + lxo - 2;
        int uy = y0 + ly - 2;
        int uz = z0 + lz - 2;
        int g  = ((uz & DSM) << 14) | ((uy & DSM) << 7) | (ux & DSM);
        float mm = __ldg(mg + g);
        if (mm != 0.0f) atomicOr(&S->OCC[r], 1ull << (lxo + 2));
        __half2 a = __floats2half2_rn(__ldg(xg + g) - (float)ux,
                                      __ldg(yg + g) - (float)uy);
        int s = lz * HXY + ly * SHX + lxo + 2;
        S->W01[s] = make_uint2(*(unsigned int*)&a,
                               pack_w01y(__ldg(zg + g) - (float)uz, __ldg(vzg + g)));
        S->W2[s]  = pack_w2(__ldg(vxg + g), __ldg(vyg + g));
    }

    // ---- Fused zeroing of this block's own output region.
    // Valid: scatter is provably intra-cell (|xn - ix| < 0.5).
    {
        const float4 z4 = make_float4(0.f, 0.f, 0.f, 0.f);
        for (int i = tid; i < CELLS * 7 / 4; i += NTHR) {
            int q   = i & 7;
            int row = (i >> 3) & 63;
            int f   = i >> 9;
            int ly  = row & 7, lz = row >> 3;
            int a = f * D3 + (((z0 + lz) << 14) | ((y0 + ly) << 7) | (x0 + q * 4));
            *(float4*)(out + a) = z4;
        }
    }
    __syncthreads();

    // ---- Warp-aggregated compaction.
    for (int q = 0; q < (CELLS + NTHR - 1) / NTHR; ++q) {
        const int i = tid + q * NTHR;
        if (i >= CELLS) break;                     // whole warps exit together
        const int lx = i & 31;
        const int ly = (i >> 5) & 7;
        const int lz = i >> 8;
        const float m = __ldg(mg + (((z0 + lz) << 14) | ((y0 + ly) << 7) | (x0 + lx)));
        unsigned bal = __ballot_sync(0xFFFFFFFFu, m != 0.0f);
        int base = 0;
        if ((tid & 31) == 0 && bal) base = atomicAdd(&S->cnt, __popc(bal));
        base = __shfl_sync(0xFFFFFFFFu, base, 0);
        if (m != 0.0f) {
            int rank = __popc(bal & ((1u << (tid & 31)) - 1u));
            S->list[base + rank] = (unsigned short)i;
        }
    }
    __syncthreads();

    const int cnt = S->cnt;
    const float KN = 500000.0f;

    for (int i = tid; i < cnt; i += NTHR) {
        const int t  = S->list[i];
        const int lx = t & 31;
        const int ly = (t >> 5) & 7;
        const int lz = t >> 8;
        const int cc = (lz + 2) * HXY + (ly + 2) * SHX + (lx + 4);
        const int g0 = (((z0 + lz) << 14) | ((y0 + ly) << 7) | (x0 + lx));

        const uint2 wc = S->W01[cc];
        const float JX = f16lo(wc.x), JY = f16hi(wc.x), JZ = f16lo(wc.y);
        const float X = (float)(x0 + lx) + JX;
        const float Y = (float)(y0 + ly) + JY;
        const float Z = (float)(z0 + lz) + JZ;
        const float VX = __ldg(vxg + g0);
        const float VY = __ldg(vyg + g0);
        const float VZ = __ldg(vzg + g0);

        float fx = 0.0f, fy = 0.0f, fz = 0.0f;

        // ---- Candidate mask: occupied neighbors among the 80 s2<=6 shifts.
        // Row r contributes 5 bits at position 5*r (m0: rows 0-11, m1: 12-20).
        u64 m0 = 0ull, m1 = 0ull;
        #pragma unroll
        for (int r = 0; r < NROW; ++r) {
            u64 bits = (S->OCC[(lz + 2 + cROZ[r]) * SHY + (ly + 2 + cROY[r])]
                        >> (lx + 2)) & (u64)cPAT[r];
            if (r < 12) m0 |= bits << (5 * r);
            else        m1 |= bits << (5 * (r - 12));
        }

        // ---- Iterate only occupied candidates (E ~16/particle).
        #define DECODE_LOOP(mvar, ROWBASE)                                    \
        while (mvar) {                                                        \
            int k = __ffsll((long long)(mvar)) - 1;                           \
            mvar &= mvar - 1;                                                 \
            int rr = (k * 13108) >> 16;            /* k/5 for k<105 */        \
            int oxm2 = k - rr * 5 - 2;                                        \
            float4 rt = S->ROWT[rr + (ROWBASE)];                              \
            int o = cc + __float_as_int(rt.x) + oxm2;                         \
            uint2 w = S->W01[o];                                              \
            float dx = (JX - (float)oxm2) - f16lo(w.x);                       \
            float dy = (JY - rt.y) - f16hi(w.x);                              \
            float dz = (JZ - rt.z) - f16lo(w.y);                              \
            float sq = fmaf(dx, dx, fmaf(dy, dy, dz * dz));                   \
            unsigned int w2 = S->W2[o];                                       \
            float rcd = fast_rsqrt(sq);                                       \
            float vnu = (VX - bflo(w2)) * dx + (VY - bfhi(w2)) * dy +         \
                        (VZ - bfhi(w.y)) * dz;                                \
            float coef = fmaf(fmaf(ETA * vnu, rcd, -1000000.0f), rcd,         \
                              500000.0f);                                     \
            coef = (sq < 4.0f) ? coef : 0.0f;                                 \
            fx = fmaf(coef, dx, fx);                                          \
            fy = fmaf(coef, dy, fy);                                          \
            fz = fmaf(coef, dz, fz);                                          \
        }
        DECODE_LOOP(m0, 0)
        DECODE_LOOP(m1, 12)
        #undef DECODE_LOOP

        // ---- Corner fallback: "contact with empty cell" needs |pos| < 2 —
        // only grid cell (1,1,1). Loop ALL shifts over EMPTY neighbors
        // (occupied s2<=6 handled above; occupied s2>=8 cannot contact).
        if (X * X + Y * Y + Z * Z < 4.0f) {
            #pragma unroll 1
            for (int oz = -2; oz <= 2; ++oz)
            #pragma unroll 1
            for (int oy = -2; oy <= 2; ++oy)
            #pragma unroll 1
            for (int ox = -2; ox <= 2; ++ox) {
                if ((ox | oy | oz) == 0) continue;
                u64 rb = S->OCC[(lz + 2 + oz) * SHY + (ly + 2 + oy)];
                if ((rb >> (lx + 4 + ox)) & 1ull) continue;   // occupied
                int o = cc + oz * HXY + oy * SHX + ox;
                uint2 w = S->W01[o];
                float dx = (JX - (float)ox) - f16lo(w.x);
                float dy = (JY - (float)oy) - f16hi(w.x);
                float dz = (JZ - (float)oz) - f16lo(w.y);
                float sq = fmaf(dx, dx, fmaf(dy, dy, dz * dz));
                if (sq < 4.0f) {
                    unsigned int w2 = S->W2[o];
                    float rcd = fast_rsqrt(sq);
                    float vnu = (VX - bflo(w2)) * dx + (VY - bfhi(w2)) * dy +
                                (VZ - bfhi(w.y)) * dz;
                    float coef = fmaf(fmaf(ETA * vnu, rcd, -1000000.0f), rcd,
                                      500000.0f);
                    fx = fmaf(coef, dx, fx);
                    fy = fmaf(coef, dy, fy);
                    fz = fmaf(coef, dz, fz);
                }
            }
        }

        // ---- Boundary overlap forces (mask == 1 for list entries)
        float bl = (X != 0.0f && X < 1.0f) ? 1.0f : 0.0f;
        float br = (X > 126.0f) ? 1.0f : 0.0f;
        float bb = (Y != 0.0f && Y < 1.0f) ? 1.0f : 0.0f;
        float bt = (Y > 126.0f) ? 1.0f : 0.0f;
        float bf = (Z != 0.0f && Z < 1.0f) ? 1.0f : 0.0f;
        float bk = (Z > 126.0f) ? 1.0f : 0.0f;
        float fxb = KN * bl * (1.0f - X) - KN * br * (X - 126.0f) - ETA * VX * (bl + br);
        float fyb = KN * bb * (1.0f - Y) - KN * bt * (Y - 126.0f) - ETA * VY * (bb + bt);
        float fzb = KN * bf * (1.0f - Z) - KN * bk * (Z - 126.0f) - ETA * VZ * (bf + bk);

        float vxn = VX + 1e-4f * (-fx + fxb);
        float vyn = VY + 1e-4f * (-9.8f - fy + fyb);
        float vzn = VZ + 1e-4f * (-fz + fzb);
        float xn = X + 1e-4f * vxn;
        float yn = Y + 1e-4f * vyn;
        float zn = Z + 1e-4f * vzn;

        // ---- Cell-list relocation (round half-even like jnp.round).
        int cx = __float2int_rn(xn);
        int cy = __float2int_rn(yn);
        int cz = __float2int_rn(zn);
        if (cx >= 1 && cx <= 127 && cy >= 1 && cy <= 127 && cz >= 1 && cz <= 127) {
            int l = (cz << 14) | (cy << 7) | cx;
            out[l]          = xn;
            out[D3 + l]     = yn;
            out[2 * D3 + l] = zn;
            out[3 * D3 + l] = vxn;
            out[4 * D3 + l] = vyn;
            out[5 * D3 + l] = vzn;
            out[6 * D3 + l] = 1.0f;
        }
    }
}

extern "C" void kernel_launch(void* const* d_in, const int* in_sizes, int n_in,
                              void* d_out, int out_size)
{
    const float* xg  = (const float*)d_in[0];
    const float* yg  = (const float*)d_in[1];
    const float* zg  = (const float*)d_in[2];
    const float* vxg = (const float*)d_in[3];
    const float* vyg = (const float*)d_in[4];
    const float* vzg = (const float*)d_in[5];
    const float* mg  = (const float*)d_in[6];
    float* out = (float*)d_out;

    // No memset: each block zeros its own tile region in-kernel.

    double alpha = -log(0.7) / M_PI;
    double gamma = alpha / sqrt(alpha * alpha + 1.0);
    float  eta   = (float)(2.0 * gamma * sqrt(500000.0 * 1.0));

    const size_t smem = sizeof(SM);   // ~74.9 KB -> 3 blocks/SM
    cudaFuncSetAttribute(dem_step, cudaFuncAttributeMaxDynamicSharedMemorySize, (int)smem);

    dim3 block(NTHR, 1, 1);
    dim3 grid(DS / TXD, DS / TYD, DS / TZD);   // 4 x 16 x 16 = 1024 blocks
    dem_step<<<grid, block, smem>>>(xg, yg, zg, vxg, vyg, vzg, mg, out, eta);
}

// round 16
// speedup vs baseline: 1.0519x; 1.0519x over previous
#include <cuda_runtime.h>
#include <cuda_fp16.h>
#include <cuda_bf16.h>
#include <math.h>

#define DS   128
#define DSM  127
#define D3   (DS * DS * DS)

// Tile: 32 x 8 x 8 real cells = 2048; 384 threads, 3 blocks/SM.
#define TXD   32
#define TYD   8
#define TZD   8
#define CELLS (TXD * TYD * TZD)  // 2048
#define NTHR  384

// Halo padded in x to 40 so interior quads are 16B-aligned for STS.128.
#define SHX  40
#define SHY  12
#define SHZ  12
#define HXY  (SHX * SHY)         // 480
#define HTOT (HXY * SHZ)         // 5760

// 12 B per halo cell, position words interleaved for one LDS.64:
//   W01[i].x = f16(jx) | f16(jy)<<16   (jitter vs UNWRAPPED halo coord;
//                                       empty cells store -u exactly)
//   W01[i].y = f16(jz) | bf16(ETA*vz)<<16
//   W2[i]    = bf16(ETA*vx) | bf16(ETA*vy)<<16
// ETA is folded into the packed velocities at fill time: saves the
// ETA*vnu FMUL in every contribution.
struct SM {
    uint2          W01[HTOT];
    unsigned int   W2[HTOT];
    unsigned short list[CELLS];
    int            cnt;
};

__device__ __forceinline__ float fast_rsqrt(float x) {
    float r; asm("rsqrt.approx.f32 %0, %1;" : "=f"(r) : "f"(x)); return r;
}
__device__ __forceinline__ float f16lo(unsigned int w) {
    return __half2float(__ushort_as_half((unsigned short)(w & 0xFFFFu)));
}
__device__ __forceinline__ float f16hi(unsigned int w) {
    return __half2float(__ushort_as_half((unsigned short)(w >> 16)));
}
__device__ __forceinline__ float bflo(unsigned int w) {
    return __uint_as_float(w << 16);
}
__device__ __forceinline__ float bfhi(unsigned int w) {
    return __uint_as_float(w & 0xFFFF0000u);
}
__device__ __forceinline__ unsigned int pack_w01y(float jz, float evz) {
    unsigned int h = __half_as_ushort(__float2half_rn(jz));
    unsigned int b = (unsigned int)__bfloat16_as_ushort(__float2bfloat16(evz));
    return (b << 16) | h;
}
__device__ __forceinline__ unsigned int pack_w2(float evx, float evy) {
    unsigned int a = (unsigned int)__bfloat16_as_ushort(__float2bfloat16(evx));
    unsigned int b = (unsigned int)__bfloat16_as_ushort(__float2bfloat16(evy));
    return (b << 16) | a;
}

// Branchless contribution (near shifts). XO/YO/ZO hoisted (JX-ox) etc.
// vnuE = ETA*vn*dist (ETA pre-folded). coef = (vnuE*rcd - 2KN)*rcd + KN.
#define CONTRIB_NB(o, XO, YO, ZO)                                             \
    {                                                                         \
        uint2 w = S->W01[(o)];                                                \
        float dx = (XO) - f16lo(w.x);                                         \
        float dy = (YO) - f16hi(w.x);                                         \
        float dz = (ZO) - f16lo(w.y);                                         \
        float sq = fmaf(dx, dx, fmaf(dy, dy, dz * dz));                       \
        unsigned int w2 = S->W2[(o)];                                         \
        float rcd = fast_rsqrt(sq);                                           \
        float vnuE = (EVX - bflo(w2)) * dx + (EVY - bfhi(w2)) * dy +          \
                     (EVZ - bfhi(w.y)) * dz;                                  \
        float coef = fmaf(fmaf(vnuE, rcd, -1000000.0f), rcd, 500000.0f);      \
        coef = (sq < 4.0f) ? coef : 0.0f;                                     \
        fx = fmaf(coef, dx, fx);                                              \
        fy = fmaf(coef, dy, fy);                                              \
        fz = fmaf(coef, dz, fz);                                              \
    }

// Far single (rare rows): branchy.
#define FAR1(o, XO, YO, ZO)                                                   \
    {                                                                         \
        uint2 w = S->W01[(o)];                                                \
        float dx = (XO) - f16lo(w.x);                                         \
        float dy = (YO) - f16hi(w.x);                                         \
        float dz = (ZO) - f16lo(w.y);                                         \
        float sq = fmaf(dx, dx, fmaf(dy, dy, dz * dz));                       \
        if (sq < 4.0f) {                                                      \
            unsigned int w2 = S->W2[(o)];                                     \
            float rcd = fast_rsqrt(sq);                                       \
            float vnuE = (EVX - bflo(w2)) * dx + (EVY - bfhi(w2)) * dy +      \
                         (EVZ - bfhi(w.y)) * dz;                              \
            float coef = fmaf(fmaf(vnuE, rcd, -1000000.0f), rcd, 500000.0f);  \
            fx = fmaf(coef, dx, fx);                                          \
            fy = fmaf(coef, dy, fy);                                          \
            fz = fmaf(coef, dz, fz);                                          \
        }                                                                     \
    }

// Far pair: one branch region for two shifts, loads issue back-to-back.
#define FAR2(oA, XA, YA, ZA, oB, XB, YB, ZB)                                  \
    {                                                                         \
        uint2 wA = S->W01[(oA)];                                              \
        uint2 wB = S->W01[(oB)];                                              \
        float dxA = (XA) - f16lo(wA.x);                                       \
        float dyA = (YA) - f16hi(wA.x);                                       \
        float dzA = (ZA) - f16lo(wA.y);                                       \
        float sqA = fmaf(dxA, dxA, fmaf(dyA, dyA, dzA * dzA));                \
        float dxB = (XB) - f16lo(wB.x);                                       \
        float dyB = (YB) - f16hi(wB.x);                                       \
        float dzB = (ZB) - f16lo(wB.y);                                       \
        float sqB = fmaf(dxB, dxB, fmaf(dyB, dyB, dzB * dzB));                \
        if (fminf(sqA, sqB) < 4.0f) {                                         \
            unsigned int w2A = S->W2[(oA)];                                   \
            unsigned int w2B = S->W2[(oB)];                                   \
            float rcdA = fast_rsqrt(sqA);                                     \
            float vnA = (EVX - bflo(w2A)) * dxA + (EVY - bfhi(w2A)) * dyA +   \
                        (EVZ - bfhi(wA.y)) * dzA;                             \
            float cA = fmaf(fmaf(vnA, rcdA, -1000000.0f), rcdA, 500000.0f);   \
            cA = (sqA < 4.0f) ? cA : 0.0f;                                    \
            float rcdB = fast_rsqrt(sqB);                                     \
            float vnB = (EVX - bflo(w2B)) * dxB + (EVY - bfhi(w2B)) * dyB +   \
                        (EVZ - bfhi(wB.y)) * dzB;                             \
            float cB = fmaf(fmaf(vnB, rcdB, -1000000.0f), rcdB, 500000.0f);   \
            cB = (sqB < 4.0f) ? cB : 0.0f;                                    \
            fx = fmaf(cA, dxA, fmaf(cB, dxB, fx));                            \
            fy = fmaf(cA, dyA, fmaf(cB, dyB, fy));                            \
            fz = fmaf(cA, dzA, fmaf(cB, dzB, fz));                            \
        }                                                                     \
    }

__global__ __launch_bounds__(NTHR, 3) void dem_step(
    const float* __restrict__ xg,  const float* __restrict__ yg,
    const float* __restrict__ zg,  const float* __restrict__ vxg,
    const float* __restrict__ vyg, const float* __restrict__ vzg,
    const float* __restrict__ mg,  float* __restrict__ out, float ETA)
{
    extern __shared__ char smraw[];
    SM* S = (SM*)smraw;

    const int x0 = blockIdx.x * TXD;
    const int y0 = blockIdx.y * TYD;
    const int z0 = blockIdx.z * TZD;
    const int tid = threadIdx.x;

    if (tid == 0) S->cnt = 0;

    // ---- Halo fill, phase A: interior quads, vectorized (16B-aligned).
    for (int i = tid; i < SHY * SHZ * 8; i += NTHR) {
        int q  = i & 7;
        int r  = i >> 3;
        int ly = r % SHY;
        int lz = r / SHY;
        int uy = y0 + ly - 2;
        int uz = z0 + lz - 2;
        int gx = x0 + 4 * q;                       // no x-wrap in interior
        int g  = ((uz & DSM) << 14) | ((uy & DSM) << 7) | gx;
        float4 X4  = __ldg((const float4*)(xg + g));
        float4 Y4  = __ldg((const float4*)(yg + g));
        float4 Z4  = __ldg((const float4*)(zg + g));
        float4 VX4 = __ldg((const float4*)(vxg + g));
        float4 VY4 = __ldg((const float4*)(vyg + g));
        float4 VZ4 = __ldg((const float4*)(vzg + g));
        float fuy = (float)uy, fuz = (float)uz;
        unsigned int x01[4];
        {
            __half2 a;
            a = __floats2half2_rn(X4.x - (float)(gx + 0), Y4.x - fuy); x01[0] = *(unsigned int*)&a;
            a = __floats2half2_rn(X4.y - (float)(gx + 1), Y4.y - fuy); x01[1] = *(unsigned int*)&a;
            a = __floats2half2_rn(X4.z - (float)(gx + 2), Y4.z - fuy); x01[2] = *(unsigned int*)&a;
            a = __floats2half2_rn(X4.w - (float)(gx + 3), Y4.w - fuy); x01[3] = *(unsigned int*)&a;
        }
        uint4 A, B, w2;
        A.x = x01[0]; A.y = pack_w01y(Z4.x - fuz, ETA * VZ4.x);
        A.z = x01[1]; A.w = pack_w01y(Z4.y - fuz, ETA * VZ4.y);
        B.x = x01[2]; B.y = pack_w01y(Z4.z - fuz, ETA * VZ4.z);
        B.z = x01[3]; B.w = pack_w01y(Z4.w - fuz, ETA * VZ4.w);
        w2.x = pack_w2(ETA * VX4.x, ETA * VY4.x);
        w2.y = pack_w2(ETA * VX4.y, ETA * VY4.y);
        w2.z = pack_w2(ETA * VX4.z, ETA * VY4.z);
        w2.w = pack_w2(ETA * VX4.w, ETA * VY4.w);
        int s = lz * HXY + ly * SHX + 4 * q + 4;   // even -> W01 16B-aligned
        *(uint4*)&S->W01[s]     = A;
        *(uint4*)&S->W01[s + 2] = B;
        *(uint4*)&S->W2[s]      = w2;
    }

    // ---- Halo fill, phase B: x-edge cells (halo lx 0,1,34,35), scalar.
    for (int i = tid; i < SHY * SHZ * 4; i += NTHR) {
        int e  = i & 3;
        int r  = i >> 2;
        int ly = r % SHY;
        int lz = r / SHY;
        int lxo = (e < 2) ? e : e + 32;            // 0,1,34,35
        int ux = x0 + lxo - 2;
        int uy = y0 + ly - 2;
        int uz = z0 + lz - 2;
        int g  = ((uz & DSM) << 14) | ((uy & DSM) << 7) | (ux & DSM);
        __half2 a = __floats2half2_rn(__ldg(xg + g) - (float)ux,
                                      __ldg(yg + g) - (float)uy);
        int s = lz * HXY + ly * SHX + lxo + 2;
        S->W01[s] = make_uint2(*(unsigned int*)&a,
                               pack_w01y(__ldg(zg + g) - (float)uz,
                                         ETA * __ldg(vzg + g)));
        S->W2[s]  = pack_w2(ETA * __ldg(vxg + g), ETA * __ldg(vyg + g));
    }

    // ---- Fused zeroing of this block's own output region.
    // Valid: scatter is provably intra-cell (|xn - ix| < 0.5).
    {
        const float4 z4 = make_float4(0.f, 0.f, 0.f, 0.f);
        for (int i = tid; i < CELLS * 7 / 4; i += NTHR) {
            int q   = i & 7;
            int row = (i >> 3) & 63;
            int f   = i >> 9;
            int ly  = row & 7, lz = row >> 3;
            int a = f * D3 + (((z0 + lz) << 14) | ((y0 + ly) << 7) | (x0 + q * 4));
            *(float4*)(out + a) = z4;
        }
    }
    __syncthreads();

    // ---- Warp-aggregated compaction.
    for (int q = 0; q < (CELLS + NTHR - 1) / NTHR; ++q) {
        const int i = tid + q * NTHR;
        if (i >= CELLS) break;                     // whole warps exit together
        const int lx = i & 31;
        const int ly = (i >> 5) & 7;
        const int lz = i >> 8;
        const float m = __ldg(mg + (((z0 + lz) << 14) | ((y0 + ly) << 7) | (x0 + lx)));
        unsigned bal = __ballot_sync(0xFFFFFFFFu, m != 0.0f);
        int base = 0;
        if ((tid & 31) == 0 && bal) base = atomicAdd(&S->cnt, __popc(bal));
        base = __shfl_sync(0xFFFFFFFFu, base, 0);
        if (m != 0.0f) {
            int rank = __popc(bal & ((1u << (tid & 31)) - 1u));
            S->list[base + rank] = (unsigned short)i;
        }
    }
    __syncthreads();

    const int cnt = S->cnt;
    const float KN = 500000.0f;

    for (int i = tid; i < cnt; i += NTHR) {
        const int t  = S->list[i];
        const int lx = t & 31;
        const int ly = (t >> 5) & 7;
        const int lz = t >> 8;
        const int cc = (lz + 2) * HXY + (ly + 2) * SHX + (lx + 4);
        const int g0 = (((z0 + lz) << 14) | ((y0 + ly) << 7) | (x0 + lx));

        const uint2 wc = S->W01[cc];
        const float JX = f16lo(wc.x), JY = f16hi(wc.x), JZ = f16lo(wc.y);
        const float X = (float)(x0 + lx) + JX;
        const float Y = (float)(y0 + ly) + JY;
        const float Z = (float)(z0 + lz) + JZ;
        // Own velocity full precision from global (latency hidden by stencil).
        const float VX = __ldg(vxg + g0);
        const float VY = __ldg(vyg + g0);
        const float VZ = __ldg(vzg + g0);
        const float EVX = ETA * VX, EVY = ETA * VY, EVZ = ETA * VZ;

        // Hoisted per-axis offsets: dx = XO[ox+2] - jx_neighbor.
        float XO[5], YO[5], ZO[5];
        #pragma unroll
        for (int k = 0; k < 5; ++k) {
            XO[k] = JX - (float)(k - 2);
            YO[k] = JY - (float)(k - 2);
            ZO[k] = JZ - (float)(k - 2);
        }

        float fx = 0.0f, fy = 0.0f, fz = 0.0f;

        // Near shifts (s^2 <= 4, 32): branchless full computation.
        #pragma unroll
        for (int oz = -2; oz <= 2; ++oz)
        #pragma unroll
        for (int oy = -2; oy <= 2; ++oy)
        #pragma unroll
        for (int ox = -2; ox <= 2; ++ox) {
            const int s2 = oz * oz + oy * oy + ox * ox;
            if (s2 == 0 || s2 > 4) continue;
            CONTRIB_NB(cc + oz * HXY + oy * SHX + ox,
                       XO[ox + 2], YO[oy + 2], ZO[oz + 2]);
        }

        // Far shifts (s^2 in {5,6}, 48): paired branches (20 pairs + 8
        // singles = 28 branch regions instead of 48).
        #pragma unroll
        for (int oz = -2; oz <= 2; ++oz)
        #pragma unroll
        for (int oy = -2; oy <= 2; ++oy) {
            const int r2 = oz * oz + oy * oy;
            const int rbase = cc + oz * HXY + oy * SHX;
            if (r2 == 1 || r2 == 2) {
                // far ox = -2, +2
                FAR2(rbase - 2, XO[0], YO[oy + 2], ZO[oz + 2],
                     rbase + 2, XO[4], YO[oy + 2], ZO[oz + 2]);
            } else if (r2 == 4) {
                // far ox = -1, +1
                FAR2(rbase - 1, XO[1], YO[oy + 2], ZO[oz + 2],
                     rbase + 1, XO[3], YO[oy + 2], ZO[oz + 2]);
            } else if (r2 == 5) {
                // far ox = -1, +1 paired; ox = 0 single
                FAR2(rbase - 1, XO[1], YO[oy + 2], ZO[oz + 2],
                     rbase + 1, XO[3], YO[oy + 2], ZO[oz + 2]);
                FAR1(rbase, XO[2], YO[oy + 2], ZO[oz + 2]);
            }
        }

        // Excluded shifts (s^2 >= 8): only via "contact with empty cell",
        // requiring |own pos| < 2 — origin corner only. Extremely rare.
        if (X * X + Y * Y + Z * Z < 4.0f) {
            #pragma unroll 1
            for (int oz = -2; oz <= 2; ++oz)
            #pragma unroll 1
            for (int oy = -2; oy <= 2; ++oy)
            #pragma unroll 1
            for (int ox = -2; ox <= 2; ++ox) {
                int s2 = oz * oz + oy * oy + ox * ox;
                if (s2 <= 6) continue;
                FAR1(cc + oz * HXY + oy * SHX + ox,
                     JX - (float)ox, JY - (float)oy, JZ - (float)oz);
            }
        }

        // Boundary overlap forces (mask == 1 for list entries)
        float bl = (X != 0.0f && X < 1.0f) ? 1.0f : 0.0f;
        float br = (X > 126.0f) ? 1.0f : 0.0f;
        float bb = (Y != 0.0f && Y < 1.0f) ? 1.0f : 0.0f;
        float bt = (Y > 126.0f) ? 1.0f : 0.0f;
        float bf = (Z != 0.0f && Z < 1.0f) ? 1.0f : 0.0f;
        float bk = (Z > 126.0f) ? 1.0f : 0.0f;
        float fxb = KN * bl * (1.0f - X) - KN * br * (X - 126.0f) - ETA * VX * (bl + br);
        float fyb = KN * bb * (1.0f - Y) - KN * bt * (Y - 126.0f) - ETA * VY * (bb + bt);
        float fzb = KN * bf * (1.0f - Z) - KN * bk * (Z - 126.0f) - ETA * VZ * (bf + bk);

        float vxn = VX + 1e-4f * (-fx + fxb);
        float vyn = VY + 1e-4f * (-9.8f - fy + fyb);
        float vzn = VZ + 1e-4f * (-fz + fzb);
        float xn = X + 1e-4f * vxn;
        float yn = Y + 1e-4f * vyn;
        float zn = Z + 1e-4f * vzn;

        // Cell-list relocation (round half-even like jnp.round).
        int cx = __float2int_rn(xn);
        int cy = __float2int_rn(yn);
        int cz = __float2int_rn(zn);
        if (cx >= 1 && cx <= 127 && cy >= 1 && cy <= 127 && cz >= 1 && cz <= 127) {
            int l = (cz << 14) | (cy << 7) | cx;
            out[l]          = xn;
            out[D3 + l]     = yn;
            out[2 * D3 + l] = zn;
            out[3 * D3 + l] = vxn;
            out[4 * D3 + l] = vyn;
            out[5 * D3 + l] = vzn;
            out[6 * D3 + l] = 1.0f;
        }
    }
}

extern "C" void kernel_launch(void* const* d_in, const int* in_sizes, int n_in,
                              void* d_out, int out_size)
{
    const float* xg  = (const float*)d_in[0];
    const float* yg  = (const float*)d_in[1];
    const float* zg  = (const float*)d_in[2];
    const float* vxg = (const float*)d_in[3];
    const float* vyg = (const float*)d_in[4];
    const float* vzg = (const float*)d_in[5];
    const float* mg  = (const float*)d_in[6];
    float* out = (float*)d_out;

    // No memset: each block zeros its own tile region in-kernel.

    double alpha = -log(0.7) / M_PI;
    double gamma = alpha / sqrt(alpha * alpha + 1.0);
    float  eta   = (float)(2.0 * gamma * sqrt(500000.0 * 1.0));

    const size_t smem = sizeof(SM);   // ~73.2 KB -> 3 blocks/SM
    cudaFuncSetAttribute(dem_step, cudaFuncAttributeMaxDynamicSharedMemorySize, (int)smem);

    dim3 block(NTHR, 1, 1);
    dim3 grid(DS / TXD, DS / TYD, DS / TZD);   // 4 x 16 x 16 = 1024 blocks
    dem_step<<<grid, block, smem>>>(xg, yg, zg, vxg, vyg, vzg, mg, out, eta);
}

// round 17
// speedup vs baseline: 1.1257x; 1.0702x over previous
#include <cuda_runtime.h>
#include <cuda_fp16.h>
#include <cuda_bf16.h>
#include <math.h>

#define DS   128
#define DSM  127
#define D3   (DS * DS * DS)

// Tile: 32 x 8 x 8 real cells = 2048; 384 threads, 3 blocks/SM.
#define TXD   32
#define TYD   8
#define TZD   8
#define CELLS (TXD * TYD * TZD)  // 2048
#define NTHR  384

// Halo padded in x to 40 so interior quads are 16B-aligned for STS.128.
#define SHX  40
#define SHY  12
#define SHZ  12
#define HXY  (SHX * SHY)         // 480
#define HTOT (HXY * SHZ)         // 5760

// 12 B per halo cell. Positions stored as 16-bit FIXED POINT:
//   u = round(8192 * (j + 4)),  j = pos - unwrapped_halo_coord (|j| <= 0.25)
//   Unpack: PRMT(w, 0x4B000000) -> float bits of (2^23 + u): ONE ALU op,
//   no F2F conversions anywhere in the stencil.
//   W01[i].x = u(jx) | u(jy)<<16
//   W01[i].y = u(jz) | bf16(ETA*8192*vz)<<16
//   W2[i]    = bf16(ETA*8192*vx) | bf16(ETA*8192*vy)<<16
// Empty cells: sentinel u = 0xFFFF in all three coords -> scaled sq >= 6.5e8,
// always above the contact threshold (2*8192)^2 = 2.68435456e8.
// All stencil math runs in x8192-scaled space; one multiply per particle
// un-scales the force at the end.
struct SM {
    uint2          W01[HTOT];
    unsigned int   W2[HTOT];
    unsigned short list[CELLS];
    int            cnt;
};

#define SCL      8192.0f
#define INV_SCL  1.220703125e-4f          /* 1/8192, exact */
#define TH_S     2.68435456e8f            /* (2*8192)^2 */
#define M2KN_S   (-8.192e9f)              /* -2*KN*8192 */
#define FBIAS    8421376.0f               /* 2^23 + 4*8192 */

__device__ __forceinline__ float fast_rsqrt(float x) {
    float r; asm("rsqrt.approx.f32 %0, %1;" : "=f"(r) : "f"(x)); return r;
}
// Fixed-point unpack: float(2^23 + u) via PRMT — single ALU instruction.
__device__ __forceinline__ float fxlo(unsigned int w) {
    return __uint_as_float(__byte_perm(w, 0x4B000000u, 0x7410));
}
__device__ __forceinline__ float fxhi(unsigned int w) {
    return __uint_as_float(__byte_perm(w, 0x4B000000u, 0x7432));
}
__device__ __forceinline__ float bflo(unsigned int w) {
    return __uint_as_float(w << 16);
}
__device__ __forceinline__ float bfhi(unsigned int w) {
    return __uint_as_float(w & 0xFFFF0000u);
}
__device__ __forceinline__ unsigned int q16(float j) {
    return (unsigned int)__float2int_rn(fmaf(j, SCL, 32768.0f));
}
__device__ __forceinline__ unsigned short bfb(float v) {
    return __bfloat16_as_ushort(__float2bfloat16(v));
}

// Branchless contribution (near shifts). XO/YO/ZO hoisted scaled offsets.
// coef = (vnu_ss*rcd_s - 2KN*8192)*rcd_s + KN  (scaled algebra; see header).
#define CONTRIB_NB(o, XO, YO, ZO)                                             \
    {                                                                         \
        uint2 w = S->W01[(o)];                                                \
        float dx = (XO) - fxlo(w.x);                                          \
        float dy = (YO) - fxhi(w.x);                                          \
        float dz = (ZO) - fxlo(w.y);                                          \
        float sq = fmaf(dx, dx, fmaf(dy, dy, dz * dz));                       \
        unsigned int w2 = S->W2[(o)];                                         \
        float rcd = fast_rsqrt(sq);                                           \
        float vnu = (EVX - bflo(w2)) * dx + (EVY - bfhi(w2)) * dy +           \
                    (EVZ - bfhi(w.y)) * dz;                                   \
        float coef = fmaf(fmaf(vnu, rcd, M2KN_S), rcd, 500000.0f);            \
        coef = (sq < TH_S) ? coef : 0.0f;                                     \
        fx = fmaf(coef, dx, fx);                                              \
        fy = fmaf(coef, dy, fy);                                              \
        fz = fmaf(coef, dz, fz);                                              \
    }

// Far single: branchy.
#define FAR1(o, XO, YO, ZO)                                                   \
    {                                                                         \
        uint2 w = S->W01[(o)];                                                \
        float dx = (XO) - fxlo(w.x);                                          \
        float dy = (YO) - fxhi(w.x);                                          \
        float dz = (ZO) - fxlo(w.y);                                          \
        float sq = fmaf(dx, dx, fmaf(dy, dy, dz * dz));                       \
        if (sq < TH_S) {                                                      \
            unsigned int w2 = S->W2[(o)];                                     \
            float rcd = fast_rsqrt(sq);                                       \
            float vnu = (EVX - bflo(w2)) * dx + (EVY - bfhi(w2)) * dy +       \
                        (EVZ - bfhi(w.y)) * dz;                               \
            float coef = fmaf(fmaf(vnu, rcd, M2KN_S), rcd, 500000.0f);        \
            fx = fmaf(coef, dx, fx);                                          \
            fy = fmaf(coef, dy, fy);                                          \
            fz = fmaf(coef, dz, fz);                                          \
        }                                                                     \
    }

// Far pair: one branch region for two shifts.
#define FAR2(oA, XA, YA, ZA, oB, XB, YB, ZB)                                  \
    {                                                                         \
        uint2 wA = S->W01[(oA)];                                              \
        uint2 wB = S->W01[(oB)];                                              \
        float dxA = (XA) - fxlo(wA.x);                                        \
        float dyA = (YA) - fxhi(wA.x);                                        \
        float dzA = (ZA) - fxlo(wA.y);                                        \
        float sqA = fmaf(dxA, dxA, fmaf(dyA, dyA, dzA * dzA));                \
        float dxB = (XB) - fxlo(wB.x);                                        \
        float dyB = (YB) - fxhi(wB.x);                                        \
        float dzB = (ZB) - fxlo(wB.y);                                        \
        float sqB = fmaf(dxB, dxB, fmaf(dyB, dyB, dzB * dzB));                \
        if (fminf(sqA, sqB) < TH_S) {                                         \
            unsigned int w2A = S->W2[(oA)];                                   \
            unsigned int w2B = S->W2[(oB)];                                   \
            float rcdA = fast_rsqrt(sqA);                                     \
            float vnA = (EVX - bflo(w2A)) * dxA + (EVY - bfhi(w2A)) * dyA +   \
                        (EVZ - bfhi(wA.y)) * dzA;                             \
            float cA = fmaf(fmaf(vnA, rcdA, M2KN_S), rcdA, 500000.0f);        \
            cA = (sqA < TH_S) ? cA : 0.0f;                                    \
            float rcdB = fast_rsqrt(sqB);                                     \
            float vnB = (EVX - bflo(w2B)) * dxB + (EVY - bfhi(w2B)) * dyB +   \
                        (EVZ - bfhi(wB.y)) * dzB;                             \
            float cB = fmaf(fmaf(vnB, rcdB, M2KN_S), rcdB, 500000.0f);        \
            cB = (sqB < TH_S) ? cB : 0.0f;                                    \
            fx = fmaf(cA, dxA, fmaf(cB, dxB, fx));                            \
            fy = fmaf(cA, dyA, fmaf(cB, dyB, fy));                            \
            fz = fmaf(cA, dzA, fmaf(cB, dzB, fz));                            \
        }                                                                     \
    }

__global__ __launch_bounds__(NTHR, 3) void dem_step(
    const float* __restrict__ xg,  const float* __restrict__ yg,
    const float* __restrict__ zg,  const float* __restrict__ vxg,
    const float* __restrict__ vyg, const float* __restrict__ vzg,
    const float* __restrict__ mg,  float* __restrict__ out, float ETA)
{
    extern __shared__ char smraw[];
    SM* S = (SM*)smraw;

    const int x0 = blockIdx.x * TXD;
    const int y0 = blockIdx.y * TYD;
    const int z0 = blockIdx.z * TZD;
    const int tid = threadIdx.x;
    const float ETA8 = ETA * SCL;

    if (tid == 0) S->cnt = 0;

    // ---- Halo fill, phase A: interior quads, vectorized (16B-aligned).
    // Empty cell detection: x == 0 exactly (occupied cells have x >= 0.8).
    for (int i = tid; i < SHY * SHZ * 8; i += NTHR) {
        int q  = i & 7;
        int r  = i >> 3;
        int ly = r % SHY;
        int lz = r / SHY;
        int uy = y0 + ly - 2;
        int uz = z0 + lz - 2;
        int gx = x0 + 4 * q;                       // no x-wrap in interior
        int g  = ((uz & DSM) << 14) | ((uy & DSM) << 7) | gx;
        float4 X4  = __ldg((const float4*)(xg + g));
        float4 Y4  = __ldg((const float4*)(yg + g));
        float4 Z4  = __ldg((const float4*)(zg + g));
        float4 VX4 = __ldg((const float4*)(vxg + g));
        float4 VY4 = __ldg((const float4*)(vyg + g));
        float4 VZ4 = __ldg((const float4*)(vzg + g));
        float fuy = (float)uy, fuz = (float)uz;
        const float* xs = &X4.x;  const float* ys = &Y4.x;
        const float* zs = &Z4.x;  const float* vxs = &VX4.x;
        const float* vys = &VY4.x; const float* vzs = &VZ4.x;
        uint4 A, B, w2;
        unsigned int p01x[4], p01y[4], pw2[4];
        #pragma unroll
        for (int k = 0; k < 4; ++k) {
            bool emp = (xs[k] == 0.0f);
            if (emp) {
                p01x[k] = 0xFFFFFFFFu;
                p01y[k] = 0x0000FFFFu;
                pw2[k]  = 0u;
            } else {
                p01x[k] = q16(xs[k] - (float)(gx + k)) | (q16(ys[k] - fuy) << 16);
                p01y[k] = q16(zs[k] - fuz) |
                          ((unsigned int)bfb(ETA8 * vzs[k]) << 16);
                pw2[k]  = (unsigned int)bfb(ETA8 * vxs[k]) |
                          ((unsigned int)bfb(ETA8 * vys[k]) << 16);
            }
        }
        A.x = p01x[0]; A.y = p01y[0]; A.z = p01x[1]; A.w = p01y[1];
        B.x = p01x[2]; B.y = p01y[2]; B.z = p01x[3]; B.w = p01y[3];
        w2.x = pw2[0]; w2.y = pw2[1]; w2.z = pw2[2]; w2.w = pw2[3];
        int s = lz * HXY + ly * SHX + 4 * q + 4;   // even -> W01 16B-aligned
        *(uint4*)&S->W01[s]     = A;
        *(uint4*)&S->W01[s + 2] = B;
        *(uint4*)&S->W2[s]      = w2;
    }

    // ---- Halo fill, phase B: x-edge cells (halo lx 0,1,34,35), scalar.
    for (int i = tid; i < SHY * SHZ * 4; i += NTHR) {
        int e  = i & 3;
        int r  = i >> 2;
        int ly = r % SHY;
        int lz = r / SHY;
        int lxo = (e < 2) ? e : e + 32;            // 0,1,34,35
        int ux = x0 + lxo - 2;
        int uy = y0 + ly - 2;
        int uz = z0 + lz - 2;
        int g  = ((uz & DSM) << 14) | ((uy & DSM) << 7) | (ux & DSM);
        float xv = __ldg(xg + g);
        int s = lz * HXY + ly * SHX + lxo + 2;
        if (xv == 0.0f) {
            S->W01[s] = make_uint2(0xFFFFFFFFu, 0x0000FFFFu);
            S->W2[s]  = 0u;
        } else {
            unsigned int w01x = q16(xv - (float)ux) |
                                (q16(__ldg(yg + g) - (float)uy) << 16);
            unsigned int w01y = q16(__ldg(zg + g) - (float)uz) |
                                ((unsigned int)bfb(ETA8 * __ldg(vzg + g)) << 16);
            S->W01[s] = make_uint2(w01x, w01y);
            S->W2[s]  = (unsigned int)bfb(ETA8 * __ldg(vxg + g)) |
                        ((unsigned int)bfb(ETA8 * __ldg(vyg + g)) << 16);
        }
    }

    // ---- Fused zeroing of this block's own output region.
    // Valid: scatter is provably intra-cell (|xn - ix| < 0.5).
    {
        const float4 z4 = make_float4(0.f, 0.f, 0.f, 0.f);
        for (int i = tid; i < CELLS * 7 / 4; i += NTHR) {
            int q   = i & 7;
            int row = (i >> 3) & 63;
            int f   = i >> 9;
            int ly  = row & 7, lz = row >> 3;
            int a = f * D3 + (((z0 + lz) << 14) | ((y0 + ly) << 7) | (x0 + q * 4));
            *(float4*)(out + a) = z4;
        }
    }
    __syncthreads();

    // ---- Warp-aggregated compaction.
    for (int q = 0; q < (CELLS + NTHR - 1) / NTHR; ++q) {
        const int i = tid + q * NTHR;
        if (i >= CELLS) break;                     // whole warps exit together
        const int lx = i & 31;
        const int ly = (i >> 5) & 7;
        const int lz = i >> 8;
        const float m = __ldg(mg + (((z0 + lz) << 14) | ((y0 + ly) << 7) | (x0 + lx)));
        unsigned bal = __ballot_sync(0xFFFFFFFFu, m != 0.0f);
        int base = 0;
        if ((tid & 31) == 0 && bal) base = atomicAdd(&S->cnt, __popc(bal));
        base = __shfl_sync(0xFFFFFFFFu, base, 0);
        if (m != 0.0f) {
            int rank = __popc(bal & ((1u << (tid & 31)) - 1u));
            S->list[base + rank] = (unsigned short)i;
        }
    }
    __syncthreads();

    const int cnt = S->cnt;
    const float KN = 500000.0f;

    for (int i = tid; i < cnt; i += NTHR) {
        const int t  = S->list[i];
        const int lx = t & 31;
        const int ly = (t >> 5) & 7;
        const int lz = t >> 8;
        const int cc = (lz + 2) * HXY + (ly + 2) * SHX + (lx + 4);
        const int g0 = (((z0 + lz) << 14) | ((y0 + ly) << 7) | (x0 + lx));

        const uint2 wc = S->W01[cc];
        const float FXs = fxlo(wc.x), FYs = fxhi(wc.x), FZs = fxlo(wc.y);
        const float X = fmaf(FXs - FBIAS, INV_SCL, (float)(x0 + lx));
        const float Y = fmaf(FYs - FBIAS, INV_SCL, (float)(y0 + ly));
        const float Z = fmaf(FZs - FBIAS, INV_SCL, (float)(z0 + lz));
        // Own velocity full precision from global (latency hidden by stencil).
        const float VX = __ldg(vxg + g0);
        const float VY = __ldg(vyg + g0);
        const float VZ = __ldg(vzg + g0);
        const float EVX = ETA8 * VX, EVY = ETA8 * VY, EVZ = ETA8 * VZ;

        // Hoisted scaled per-axis offsets: dx_s = XO[ox+2] - F_neighbor.
        float XO[5], YO[5], ZO[5];
        #pragma unroll
        for (int k = 0; k < 5; ++k) {
            XO[k] = FXs - (float)((k - 2) * 8192);
            YO[k] = FYs - (float)((k - 2) * 8192);
            ZO[k] = FZs - (float)((k - 2) * 8192);
        }

        float fx = 0.0f, fy = 0.0f, fz = 0.0f;   // scaled accumulators

        // Near shifts (s^2 <= 4, 32): branchless full computation.
        #pragma unroll
        for (int oz = -2; oz <= 2; ++oz)
        #pragma unroll
        for (int oy = -2; oy <= 2; ++oy)
        #pragma unroll
        for (int ox = -2; ox <= 2; ++ox) {
            const int s2 = oz * oz + oy * oy + ox * ox;
            if (s2 == 0 || s2 > 4) continue;
            CONTRIB_NB(cc + oz * HXY + oy * SHX + ox,
                       XO[ox + 2], YO[oy + 2], ZO[oz + 2]);
        }

        // Far shifts (s^2 in {5,6}, 48): paired branches.
        #pragma unroll
        for (int oz = -2; oz <= 2; ++oz)
        #pragma unroll
        for (int oy = -2; oy <= 2; ++oy) {
            const int r2 = oz * oz + oy * oy;
            const int rbase = cc + oz * HXY + oy * SHX;
            if (r2 == 1 || r2 == 2) {
                FAR2(rbase - 2, XO[0], YO[oy + 2], ZO[oz + 2],
                     rbase + 2, XO[4], YO[oy + 2], ZO[oz + 2]);
            } else if (r2 == 4) {
                FAR2(rbase - 1, XO[1], YO[oy + 2], ZO[oz + 2],
                     rbase + 1, XO[3], YO[oy + 2], ZO[oz + 2]);
            } else if (r2 == 5) {
                FAR2(rbase - 1, XO[1], YO[oy + 2], ZO[oz + 2],
                     rbase + 1, XO[3], YO[oy + 2], ZO[oz + 2]);
                FAR1(rbase, XO[2], YO[oy + 2], ZO[oz + 2]);
            }
        }

        // Un-scale forces to real units.
        fx *= INV_SCL; fy *= INV_SCL; fz *= INV_SCL;

        // Corner fallback: "contact with empty cell" needs |pos| < 2 — only
        // grid cell (1,1,1). Every EMPTY neighbor (pos 0) contributes the
        // SAME force (depends only on own pos/vel): count sentinels over all
        // 124 shifts and apply once. Occupied neighbors are fully handled by
        // the main loops (occupied s^2 >= 8 provably cannot contact).
        float sqo = X * X + Y * Y + Z * Z;
        if (sqo < 4.0f) {
            int ne = 0;
            #pragma unroll 1
            for (int oz = -2; oz <= 2; ++oz)
            #pragma unroll 1
            for (int oy = -2; oy <= 2; ++oy)
            #pragma unroll 1
            for (int ox = -2; ox <= 2; ++ox) {
                if ((ox | oy | oz) == 0) continue;
                if (S->W01[cc + oz * HXY + oy * SHX + ox].x == 0xFFFFFFFFu) ++ne;
            }
            float rcd = fast_rsqrt(sqo);
            float vnu = VX * X + VY * Y + VZ * Z;
            float coef = fmaf(fmaf(ETA * vnu, rcd, -1000000.0f), rcd, KN);
            float s = (float)ne * coef;
            fx = fmaf(s, X, fx);
            fy = fmaf(s, Y, fy);
            fz = fmaf(s, Z, fz);
        }

        // Boundary overlap forces (mask == 1 for list entries)
        float bl = (X != 0.0f && X < 1.0f) ? 1.0f : 0.0f;
        float br = (X > 126.0f) ? 1.0f : 0.0f;
        float bb = (Y != 0.0f && Y < 1.0f) ? 1.0f : 0.0f;
        float bt = (Y > 126.0f) ? 1.0f : 0.0f;
        float bf = (Z != 0.0f && Z < 1.0f) ? 1.0f : 0.0f;
        float bk = (Z > 126.0f) ? 1.0f : 0.0f;
        float fxb = KN * bl * (1.0f - X) - KN * br * (X - 126.0f) - ETA * VX * (bl + br);
        float fyb = KN * bb * (1.0f - Y) - KN * bt * (Y - 126.0f) - ETA * VY * (bb + bt);
        float fzb = KN * bf * (1.0f - Z) - KN * bk * (Z - 126.0f) - ETA * VZ * (bf + bk);

        float vxn = VX + 1e-4f * (-fx + fxb);
        float vyn = VY + 1e-4f * (-9.8f - fy + fyb);
        float vzn = VZ + 1e-4f * (-fz + fzb);
        float xn = X + 1e-4f * vxn;
        float yn = Y + 1e-4f * vyn;
        float zn = Z + 1e-4f * vzn;

        // Cell-list relocation (round half-even like jnp.round).
        int cx = __float2int_rn(xn);
        int cy = __float2int_rn(yn);
        int cz = __float2int_rn(zn);
        if (cx >= 1 && cx <= 127 && cy >= 1 && cy <= 127 && cz >= 1 && cz <= 127) {
            int l = (cz << 14) | (cy << 7) | cx;
            out[l]          = xn;
            out[D3 + l]     = yn;
            out[2 * D3 + l] = zn;
            out[3 * D3 + l] = vxn;
            out[4 * D3 + l] = vyn;
            out[5 * D3 + l] = vzn;
            out[6 * D3 + l] = 1.0f;
        }
    }
}

extern "C" void kernel_launch(void* const* d_in, const int* in_sizes, int n_in,
                              void* d_out, int out_size)
{
    const float* xg  = (const float*)d_in[0];
    const float* yg  = (const float*)d_in[1];
    const float* zg  = (const float*)d_in[2];
    const float* vxg = (const float*)d_in[3];
    const float* vyg = (const float*)d_in[4];
    const float* vzg = (const float*)d_in[5];
    const float* mg  = (const float*)d_in[6];
    float* out = (float*)d_out;

    // No memset: each block zeros its own tile region in-kernel.

    double alpha = -log(0.7) / M_PI;
    double gamma = alpha / sqrt(alpha * alpha + 1.0);
    float  eta   = (float)(2.0 * gamma * sqrt(500000.0 * 1.0));

    const size_t smem = sizeof(SM);   // ~73.2 KB -> 3 blocks/SM
    cudaFuncSetAttribute(dem_step, cudaFuncAttributeMaxDynamicSharedMemorySize, (int)smem);

    dim3 block(NTHR, 1, 1);
    dim3 grid(DS / TXD, DS / TYD, DS / TZD);   // 4 x 16 x 16 = 1024 blocks
    dem_step<<<grid, block, smem>>>(xg, yg, zg, vxg, vyg, vzg, mg, out, eta);
}